// round 2
// baseline (speedup 1.0000x reference)
#include <cuda_runtime.h>
#include <stdint.h>

#define BATCH   16
#define NANCH   261888          // 3 * (65536+16384+4096+1024+256)
#define TOPK    1000
#define CAP     4096            // candidate capacity per image (expected ~1300 max)
#define NBINS   65536
#define NLEV    5

// ---- static level tables -------------------------------------------------
__constant__ int   c_HW[NLEV]     = {65536, 16384, 4096, 1024, 256};
__constant__ int   c_W[NLEV]      = {256, 128, 64, 32, 16};
__constant__ float c_stride[NLEV] = {4.f, 8.f, 16.f, 32.f, 64.f};
__constant__ float c_size[NLEV]   = {32.f, 64.f, 128.f, 256.f, 512.f};
// level block offsets in anchor space (= 3*HW cumulative)
__constant__ int   c_off[NLEV]    = {0, 196608, 245760, 258048, 261120};

__device__ __forceinline__ int level_of(int j, int& rem) {
    if (j < 196608) { rem = j;          return 0; }
    if (j < 245760) { rem = j - 196608; return 1; }
    if (j < 258048) { rem = j - 245760; return 2; }
    if (j < 261120) { rem = j - 258048; return 3; }
    rem = j - 261120; return 4;
}

// ---- scratch (static device globals; no allocation anywhere) -------------
static __device__ unsigned int       g_keys[BATCH * NANCH];   // sigmoid bits, cls layout
static __device__ unsigned int       g_hist[BATCH * NBINS];
static __device__ unsigned int       g_thr16[BATCH];
static __device__ unsigned int       g_cnt[BATCH];
static __device__ unsigned long long g_cand[BATCH * CAP];
static __device__ unsigned int       g_selA[BATCH * TOPK];
static __device__ unsigned int       g_selU[BATCH * TOPK];
static __device__ float g_cx[BATCH*TOPK], g_cy[BATCH*TOPK], g_w[BATCH*TOPK], g_h[BATCH*TOPK];
static __device__ float g_sc[BATCH*TOPK];
static __device__ float g_bx1[BATCH*TOPK], g_by1[BATCH*TOPK], g_bx2[BATCH*TOPK], g_by2[BATCH*TOPK];
static __device__ float g_ar[BATCH*TOPK];
static __device__ unsigned int       g_mask[BATCH * TOPK * 32];
static __device__ unsigned char      g_keep[BATCH * TOPK];

// precise sigmoid matching XLA logistic expansion: 1 / (1 + exp(-x))
__device__ __forceinline__ float sigmoid_precise(float x) {
    return __fdiv_rn(1.0f, __fadd_rn(1.0f, expf(-x)));
}

// ---- K1: sigmoid -> sortable key (positive float bits) + 16-bit histogram
__global__ void k_keys(const float* __restrict__ c0, const float* __restrict__ c1,
                       const float* __restrict__ c2, const float* __restrict__ c3,
                       const float* __restrict__ c4) {
    int idx = blockIdx.x * 256 + threadIdx.x;
    if (idx >= BATCH * NANCH) return;
    int b = idx / NANCH, j = idx - b * NANCH;
    int rem; int lev = level_of(j, rem);
    const float* p = (lev == 0) ? c0 : (lev == 1) ? c1 : (lev == 2) ? c2 : (lev == 3) ? c3 : c4;
    float x = p[(size_t)b * 3 * c_HW[lev] + rem];      // channel-major layout: coalesced
    unsigned u = __float_as_uint(sigmoid_precise(x));  // in (0,1): int-order == float-order
    g_keys[idx] = u;
    atomicAdd(&g_hist[b * NBINS + (u >> 16)], 1u);
}

// ---- K2: per-image 16-bit threshold: max t with count(u>>16 >= t) >= TOPK
__global__ void k_thr() {
    int b = blockIdx.x, t = threadIdx.x;   // 256 threads
    __shared__ unsigned csum[256];
    __shared__ unsigned suf[256];
    const unsigned* h = g_hist + b * NBINS;
    int base = t * 256;
    unsigned s = 0;
#pragma unroll 8
    for (int i = 0; i < 256; i++) s += h[base + i];
    csum[t] = s;
    __syncthreads();
    if (t == 0) {
        unsigned run = 0;
        for (int ch = 255; ch >= 0; ch--) { suf[ch] = run; run += csum[ch]; }
    }
    __syncthreads();
    unsigned run = suf[t];
    if (run < TOPK && run + csum[t] >= TOPK) {
        for (int bin = base + 255; bin >= base; bin--) {
            run += h[bin];
            if (run >= TOPK) { g_thr16[b] = (unsigned)bin; break; }
        }
    }
}

// ---- K3: compact candidates (key64 = score_bits<<32 | ~anchor_index)
__global__ void k_compact() {
    int idx = blockIdx.x * 256 + threadIdx.x;
    if (idx >= BATCH * NANCH) return;
    int b = idx / NANCH, j = idx - b * NANCH;
    unsigned u = g_keys[idx];
    if ((u >> 16) >= g_thr16[b]) {
        int rem; int lev = level_of(j, rem);
        int HW = c_HW[lev];
        int k = rem / HW, cell = rem - k * HW;
        unsigned a = (unsigned)(c_off[lev] + cell * 3 + k);
        unsigned pos = atomicAdd(&g_cnt[b], 1u);
        if (pos < CAP)
            g_cand[b * CAP + pos] =
                ((unsigned long long)u << 32) | (unsigned long long)(0xFFFFFFFFu - a);
    }
}

// ---- K4: per-image bitonic sort (descending) of 4096 keys, emit top-1000
__global__ void k_sort() {
    __shared__ unsigned long long sh[CAP];   // 32 KB
    int b = blockIdx.x, tid = threadIdx.x;   // 1024 threads
    unsigned n = g_cnt[b]; if (n > CAP) n = CAP;
    for (int i = tid; i < CAP; i += 1024) sh[i] = (i < (int)n) ? g_cand[b * CAP + i] : 0ULL;
    __syncthreads();
    for (int size = 2; size <= CAP; size <<= 1) {
        for (int stride = size >> 1; stride > 0; stride >>= 1) {
            for (int l = tid; l < CAP; l += 1024) {
                int p = l ^ stride;
                if (p > l) {
                    bool descBlock = ((l & size) == 0);
                    unsigned long long x = sh[l], y = sh[p];
                    bool sw = descBlock ? (x < y) : (x > y);
                    if (sw) { sh[l] = y; sh[p] = x; }
                }
            }
            __syncthreads();
        }
    }
    for (int i = tid; i < TOPK; i += 1024) {
        unsigned long long key = sh[i];
        g_selU[b * TOPK + i] = (unsigned)(key >> 32);
        g_selA[b * TOPK + i] = 0xFFFFFFFFu - (unsigned)(key & 0xFFFFFFFFull);
    }
}

// ---- K5: decode the selected 16x1000 boxes
__global__ void k_decode(const float* __restrict__ b0, const float* __restrict__ b1,
                         const float* __restrict__ b2, const float* __restrict__ b3,
                         const float* __restrict__ b4) {
    int i = blockIdx.x * 256 + threadIdx.x;
    if (i >= BATCH * TOPK) return;
    int b = i / TOPK;
    int a = (int)g_selA[i];
    float score = __uint_as_float(g_selU[i]);
    int rem; int lev = level_of(a, rem);
    int cell = rem / 3, k = rem - cell * 3;
    int W = c_W[lev], HW = c_HW[lev];
    int hh = cell / W, ww = cell - hh * W;
    float st = c_stride[lev], sz = c_size[lev];
    float acx = ((float)ww + 0.5f) * st;
    float acy = ((float)hh + 0.5f) * st;
    float ratio = (k == 0) ? 0.5f : (k == 1) ? 1.0f : 2.0f;
    float sr = __fsqrt_rn(ratio);
    float aw = __fdiv_rn(sz, sr);
    float ah = sz * sr;
    const float* bp = (lev == 0) ? b0 : (lev == 1) ? b1 : (lev == 2) ? b2 : (lev == 3) ? b3 : b4;
    size_t base = (size_t)b * 12 * HW + (size_t)k * 4 * HW + cell;
    float d0 = bp[base], d1 = bp[base + HW], d2 = bp[base + 2 * (size_t)HW], d3 = bp[base + 3 * (size_t)HW];
    float cx = acx + d0 * aw;
    float cy = acy + d1 * ah;
    float w  = aw * expf(fminf(fmaxf(d2, -4.0f), 4.0f));
    float h  = ah * expf(fminf(fmaxf(d3, -4.0f), 4.0f));
    g_cx[i] = cx; g_cy[i] = cy; g_w[i] = w; g_h[i] = h; g_sc[i] = score;
    float x1 = cx - w * 0.5f, y1 = cy - h * 0.5f;
    float x2 = cx + w * 0.5f, y2 = cy + h * 0.5f;
    g_bx1[i] = x1; g_by1[i] = y1; g_bx2[i] = x2; g_by2[i] = y2;
    g_ar[i] = (x2 - x1) * (y2 - y1);
}

// ---- K6: NMS pairwise suppression bitmask (rows i, 32 words of j-bits)
__global__ void k_mask() {
    __shared__ float sx1[TOPK], sy1[TOPK], sx2[TOPK], sy2[TOPK], sar[TOPK];
    int b = blockIdx.y;
    int tid = threadIdx.y * 32 + threadIdx.x;
    for (int i = tid; i < TOPK; i += 1024) {
        int g = b * TOPK + i;
        sx1[i] = g_bx1[g]; sy1[i] = g_by1[g];
        sx2[i] = g_bx2[g]; sy2[i] = g_by2[g];
        sar[i] = g_ar[g];
    }
    __syncthreads();
    int i = blockIdx.x * 32 + threadIdx.y;
    if (i < TOPK) {
        float x1 = sx1[i], y1 = sy1[i], x2 = sx2[i], y2 = sy2[i], ar = sar[i];
        unsigned bits = 0;
        int j0 = threadIdx.x * 32;
#pragma unroll 4
        for (int jj = 0; jj < 32; jj++) {
            int j = j0 + jj;
            if (j < TOPK && j > i) {
                float iw = fmaxf(fminf(x2, sx2[j]) - fmaxf(x1, sx1[j]), 0.0f);
                float ih = fmaxf(fminf(y2, sy2[j]) - fmaxf(y1, sy1[j]), 0.0f);
                float inter = iw * ih;
                float iou = inter / (ar + sar[j] - inter + 1e-6f);
                if (iou > 0.7f) bits |= (1u << jj);
            }
        }
        g_mask[((size_t)b * TOPK + i) * 32 + threadIdx.x] = bits;
    }
}

// ---- K7: greedy NMS reduce (mask in smem, warp-serial)
__global__ void k_reduce() {
    extern __shared__ unsigned shm[];   // TOPK*32 words = 128000 B
    int b = blockIdx.x, tid = threadIdx.x;  // 1024 threads
    const unsigned* mrow = g_mask + (size_t)b * TOPK * 32;
    for (int i = tid; i < TOPK * 32; i += 1024) shm[i] = mrow[i];
    __syncthreads();
    if (tid < 32) {
        unsigned remv = 0;
        for (int i = 0; i < TOPK; i++) {
            unsigned rm = __shfl_sync(0xffffffffu, remv, i >> 5);
            bool removed = (rm >> (i & 31)) & 1u;
            if (!removed) {
                if (tid == 0) g_keep[b * TOPK + i] = 1;
                remv |= shm[i * 32 + tid];
            } else {
                if (tid == 0) g_keep[b * TOPK + i] = 0;
            }
        }
    }
}

// ---- K8: scatter kept boxes (+score) and keep mask into zeroed output
__global__ void k_scatter(float* __restrict__ out, float* __restrict__ keepF) {
    int i = blockIdx.x * 256 + threadIdx.x;
    if (i >= BATCH * TOPK) return;
    if (!g_keep[i]) return;
    int b = i / TOPK;
    size_t base = (size_t)b * NANCH + g_selA[i];
    float* o = out + base * 5;
    o[0] = g_cx[i]; o[1] = g_cy[i]; o[2] = g_w[i]; o[3] = g_h[i]; o[4] = g_sc[i];
    if (keepF) keepF[base] = 1.0f;
}

// ---- launch --------------------------------------------------------------
extern "C" void kernel_launch(void* const* d_in, const int* in_sizes, int n_in,
                              void* d_out, int out_size) {
    if (n_in < 10) return;
    const float* cls[5]; const float* bbx[5];
    // Detect ordering: interleaved (cls_p2,bbox_p2,...) has in_sizes[1]=12582912;
    // grouped (cls_p2..p6,bbox_p2..p6) has in_sizes[1]=786432.
    if (in_sizes[1] == 786432) {
        for (int l = 0; l < 5; l++) { cls[l] = (const float*)d_in[l]; bbx[l] = (const float*)d_in[5 + l]; }
    } else {
        for (int l = 0; l < 5; l++) { cls[l] = (const float*)d_in[2 * l]; bbx[l] = (const float*)d_in[2 * l + 1]; }
    }

    void* pHist = nullptr; void* pCnt = nullptr;
    cudaGetSymbolAddress(&pHist, g_hist);
    cudaGetSymbolAddress(&pCnt,  g_cnt);
    cudaMemsetAsync(pHist, 0, sizeof(unsigned) * BATCH * NBINS, 0);
    cudaMemsetAsync(pCnt,  0, sizeof(unsigned) * BATCH, 0);
    cudaMemsetAsync(d_out, 0, (size_t)out_size * sizeof(float), 0);

    const long long BA = (long long)BATCH * NANCH;
    float* keepF = nullptr;
    if ((long long)out_size >= BA * 6) keepF = (float*)d_out + BA * 5;

    static bool attr_done = false;
    if (!attr_done) {
        cudaFuncSetAttribute(k_reduce, cudaFuncAttributeMaxDynamicSharedMemorySize, TOPK * 32 * 4);
        attr_done = true;
    }

    int nba = (BATCH * NANCH + 255) / 256;   // 16368
    k_keys<<<nba, 256>>>(cls[0], cls[1], cls[2], cls[3], cls[4]);
    k_thr<<<BATCH, 256>>>();
    k_compact<<<nba, 256>>>();
    k_sort<<<BATCH, 1024>>>();
    k_decode<<<(BATCH * TOPK + 255) / 256, 256>>>(bbx[0], bbx[1], bbx[2], bbx[3], bbx[4]);
    k_mask<<<dim3((TOPK + 31) / 32, BATCH), dim3(32, 32)>>>();
    k_reduce<<<BATCH, 1024, TOPK * 32 * 4>>>();
    k_scatter<<<(BATCH * TOPK + 255) / 256, 256>>>((float*)d_out, keepF);
}